// round 11
// baseline (speedup 1.0000x reference)
#include <cuda_runtime.h>
#include <math.h>

#define MAXN 4096
#define MAXS 27
#define NGRID 10
#define NCELL (NGRID * NGRID * NGRID)
#define MAXPA 192
#define CAP 64
#define SGRID 148   // persistent search grid: one block per SM, no wave quantization

__device__ float  g_w[MAXN * 3];
__device__ float  g_shifts2[MAXS * 3];
__device__ int    g_S;
__device__ float  g_com2[3], g_minc2[3], g_maxc2[3];
__device__ int    g_fill[NCELL];          // zero at load; re-zeroed by k_write every run
__device__ float4 g_buck[NCELL * CAP];    // 1 MB fixed-capacity buckets
__device__ int    g_slab[MAXN * MAXPA];
__device__ int    g_cnt[MAXN];

#define MUL(a, b) __fmul_rn((a), (b))
#define ADD(a, b) __fadd_rn((a), (b))
#define SUB(a, b) __fsub_rn((a), (b))
#define DIV(a, b) __fdiv_rn((a), (b))

__device__ __forceinline__ unsigned fkey(float f) {
    unsigned u = __float_as_uint(f);
    return (u & 0x80000000u) ? ~u : (u | 0x80000000u);
}
__device__ __forceinline__ float fdec(unsigned k) {
    unsigned u = (k & 0x80000000u) ? (k & 0x7fffffffu) : ~k;
    return __uint_as_float(u);
}

// ---------------- kernel 1: setup + wrap + COM + min/max (ONE block) ----------------
__global__ __launch_bounds__(1024, 1)
void k_prep(const float* __restrict__ cell, const int* __restrict__ period,
            const float* __restrict__ coords, const float* __restrict__ mass, int N) {
    __shared__ float sinv[9], sfrac0[3];
    __shared__ double sd[4096];
    __shared__ unsigned skey6[32][6];
    __shared__ float scom[3];
    int t = threadIdx.x, lane = t & 31, wid = t >> 5;

    if (t == 0) {
        float m00 = cell[0], m01 = cell[1], m02 = cell[2];
        float m10 = cell[3], m11 = cell[4], m12 = cell[5];
        float m20 = cell[6], m21 = cell[7], m22 = cell[8];
        float c00 = SUB(MUL(m11, m22), MUL(m12, m21));
        float c10 = SUB(MUL(m12, m20), MUL(m10, m22));
        float c20 = SUB(MUL(m10, m21), MUL(m11, m20));
        float det = ADD(ADD(MUL(m00, c00), MUL(m01, c10)), MUL(m02, c20));
        sinv[0] = DIV(c00, det);
        sinv[1] = DIV(SUB(MUL(m02, m21), MUL(m01, m22)), det);
        sinv[2] = DIV(SUB(MUL(m01, m12), MUL(m02, m11)), det);
        sinv[3] = DIV(c10, det);
        sinv[4] = DIV(SUB(MUL(m00, m22), MUL(m02, m20)), det);
        sinv[5] = DIV(SUB(MUL(m02, m10), MUL(m00, m12)), det);
        sinv[6] = DIV(c20, det);
        sinv[7] = DIV(SUB(MUL(m01, m20), MUL(m00, m21)), det);
        sinv[8] = DIV(SUB(MUL(m00, m11), MUL(m01, m10)), det);
        float x0 = coords[0], y0 = coords[1], z0 = coords[2];
        for (int d = 0; d < 3; d++)
            sfrac0[d] = ADD(ADD(MUL(x0, sinv[0 + d]), MUL(y0, sinv[3 + d])), MUL(z0, sinv[6 + d]));
        int nrep[3];
        for (int i = 0; i < 3; i++) {
            float r = DIV(5.0f, fabsf(cell[0 + i]));
            float r1 = DIV(5.0f, fabsf(cell[3 + i]));
            float r2 = DIV(5.0f, fabsf(cell[6 + i]));
            if (r1 < r) r = r1;
            if (r2 < r) r = r2;
            nrep[i] = (int)ceilf(r) * period[i];
        }
        int idx = 0;
        for (int a = -nrep[0]; a <= nrep[0]; a++)
            for (int bb = -nrep[1]; bb <= nrep[1]; bb++)
                for (int c = -nrep[2]; c <= nrep[2]; c++) {
                    if (idx < MAXS) {
                        float fa = (float)a, fb = (float)bb, fc = (float)c;
                        for (int d = 0; d < 3; d++)
                            g_shifts2[idx * 3 + d] =
                                ADD(ADD(MUL(fa, cell[0 + d]), MUL(fb, cell[3 + d])), MUL(fc, cell[6 + d]));
                    }
                    idx++;
                }
        g_S = (idx > MAXS) ? MAXS : idx;
    }
    __syncthreads();

    // wrap all atoms (same fp chain as R10's k_wrap)
    for (int i = t; i < N; i += 1024) {
        float x = coords[i * 3 + 0], y = coords[i * 3 + 1], z = coords[i * 3 + 2];
        float f[3];
        for (int d = 0; d < 3; d++)
            f[d] = ADD(ADD(MUL(x, sinv[0 + d]), MUL(y, sinv[3 + d])), MUL(z, sinv[6 + d]));
        for (int d = 0; d < 3; d++)
            f[d] = SUB(f[d], rintf(SUB(f[d], sfrac0[d])));
        g_w[i * 3 + 0] = ADD(ADD(MUL(f[0], cell[0]), MUL(f[1], cell[3])), MUL(f[2], cell[6]));
        g_w[i * 3 + 1] = ADD(ADD(MUL(f[0], cell[1]), MUL(f[1], cell[4])), MUL(f[2], cell[7]));
        g_w[i * 3 + 2] = ADD(ADD(MUL(f[0], cell[2]), MUL(f[1], cell[5])), MUL(f[2], cell[8]));
    }
    __syncthreads();

    // COM: bit-identical accumulation order (stride-1024 + tree 512..32 + shfl tail)
    double s0 = 0.0, s1 = 0.0, s2 = 0.0, s3 = 0.0;
    for (int i = t; i < N; i += 1024) {
        double m = (double)mass[i];
        s0 += m * (double)g_w[i * 3 + 0];
        s1 += m * (double)g_w[i * 3 + 1];
        s2 += m * (double)g_w[i * 3 + 2];
        s3 += m;
    }
    sd[t] = s0; sd[1024 + t] = s1; sd[2048 + t] = s2; sd[3072 + t] = s3;
    __syncthreads();
#pragma unroll
    for (int off = 512; off >= 32; off >>= 1) {
        if (t < off) {
            sd[t] += sd[t + off];
            sd[1024 + t] += sd[1024 + t + off];
            sd[2048 + t] += sd[2048 + t + off];
            sd[3072 + t] += sd[3072 + t + off];
        }
        __syncthreads();
    }
    if (wid == 0) {
        double x0 = sd[lane], x1 = sd[1024 + lane], x2 = sd[2048 + lane], x3 = sd[3072 + lane];
#pragma unroll
        for (int off = 16; off >= 1; off >>= 1) {
            x0 += __shfl_down_sync(0xffffffffu, x0, off);
            x1 += __shfl_down_sync(0xffffffffu, x1, off);
            x2 += __shfl_down_sync(0xffffffffu, x2, off);
            x3 += __shfl_down_sync(0xffffffffu, x3, off);
        }
        if (lane == 0) {
            float sm = (float)x3;
            scom[0] = DIV((float)x0, sm);
            scom[1] = DIV((float)x1, sm);
            scom[2] = DIV((float)x2, sm);
            g_com2[0] = scom[0]; g_com2[1] = scom[1]; g_com2[2] = scom[2];
        }
    }
    __syncthreads();

    unsigned kmn[3] = {~0u, ~0u, ~0u}, kmx[3] = {0u, 0u, 0u};
    for (int i = t; i < N; i += 1024) {
        unsigned k0 = fkey(SUB(g_w[i * 3 + 0], scom[0]));
        unsigned k1 = fkey(SUB(g_w[i * 3 + 1], scom[1]));
        unsigned k2 = fkey(SUB(g_w[i * 3 + 2], scom[2]));
        kmn[0] = min(kmn[0], k0); kmx[0] = max(kmx[0], k0);
        kmn[1] = min(kmn[1], k1); kmx[1] = max(kmx[1], k1);
        kmn[2] = min(kmn[2], k2); kmx[2] = max(kmx[2], k2);
    }
#pragma unroll
    for (int o = 16; o; o >>= 1) {
#pragma unroll
        for (int d = 0; d < 3; d++) {
            kmn[d] = min(kmn[d], __shfl_xor_sync(0xffffffffu, kmn[d], o));
            kmx[d] = max(kmx[d], __shfl_xor_sync(0xffffffffu, kmx[d], o));
        }
    }
    if (lane == 0) {
#pragma unroll
        for (int d = 0; d < 3; d++) {
            skey6[wid][d] = kmn[d];
            skey6[wid][3 + d] = kmx[d];
        }
    }
    __syncthreads();
    if (wid == 0) {
        unsigned vn0 = skey6[lane][0], vn1 = skey6[lane][1], vn2 = skey6[lane][2];
        unsigned vx0 = skey6[lane][3], vx1 = skey6[lane][4], vx2 = skey6[lane][5];
#pragma unroll
        for (int o = 16; o; o >>= 1) {
            vn0 = min(vn0, __shfl_xor_sync(0xffffffffu, vn0, o));
            vn1 = min(vn1, __shfl_xor_sync(0xffffffffu, vn1, o));
            vn2 = min(vn2, __shfl_xor_sync(0xffffffffu, vn2, o));
            vx0 = max(vx0, __shfl_xor_sync(0xffffffffu, vx0, o));
            vx1 = max(vx1, __shfl_xor_sync(0xffffffffu, vx1, o));
            vx2 = max(vx2, __shfl_xor_sync(0xffffffffu, vx2, o));
        }
        if (lane == 0) {
            float mn0 = SUB(SUB(fdec(vn0), 5.0f), 1e-6f);
            float mn1 = SUB(SUB(fdec(vn1), 5.0f), 1e-6f);
            float mn2 = SUB(SUB(fdec(vn2), 5.0f), 1e-6f);
            g_minc2[0] = mn0; g_minc2[1] = mn1; g_minc2[2] = mn2;
            g_maxc2[0] = ADD(SUB(fdec(vx0), mn0), 5.0f);
            g_maxc2[1] = ADD(SUB(fdec(vx1), mn1), 5.0f);
            g_maxc2[2] = ADD(SUB(fdec(vx2), mn2), 5.0f);
        }
    }
}

// ---------------- kernel 2: images -> fixed-capacity buckets (one thread per image) --------
__global__ void k_image(int N) {
    int gt = blockIdx.x * 256 + threadIdx.x;
    int NS = g_S * N;
    if (gt >= NS) return;
    int s = gt / N;
    int a = gt - s * N;
    float c2x = SUB(SUB(g_w[a * 3 + 0], g_com2[0]), g_minc2[0]);
    float c2y = SUB(SUB(g_w[a * 3 + 1], g_com2[1]), g_minc2[1]);
    float c2z = SUB(SUB(g_w[a * 3 + 2], g_com2[2]), g_minc2[2]);
    float v0 = ADD(c2x, g_shifts2[s * 3 + 0]);
    float v1 = ADD(c2y, g_shifts2[s * 3 + 1]);
    float v2 = ADD(c2z, g_shifts2[s * 3 + 2]);
    if ((v0 > 0.f) && (v0 < g_maxc2[0]) && (v1 > 0.f) && (v1 < g_maxc2[1]) &&
        (v2 > 0.f) && (v2 < g_maxc2[2])) {
        int cx = min(max((int)floorf(DIV(v0, 5.0f)), 0), NGRID - 1);
        int cy = min(max((int)floorf(DIV(v1, 5.0f)), 0), NGRID - 1);
        int cz = min(max((int)floorf(DIV(v2, 5.0f)), 0), NGRID - 1);
        int c = cx + NGRID * (cy + NGRID * cz);
        int pos = atomicAdd(&g_fill[c], 1);
        if (pos < CAP)
            g_buck[c * CAP + pos] = make_float4(v0, v1, v2, __int_as_float(gt));
    }
}

// ---------------- kernel 3: persistent per-atom search, x2-unrolled loads ----------------
__global__ __launch_bounds__(256, 1)
void k_search(int N) {
    __shared__ int sj[8][MAXPA];
    __shared__ int spre[8][32];
    __shared__ int sadj[8][32];
    int t = threadIdx.x, lane = t & 31, wid = t >> 5;
    const int NW = SGRID * 8;

    for (int w = blockIdx.x * 8 + wid; w < N; w += NW) {
        float cx = SUB(SUB(g_w[w * 3 + 0], g_com2[0]), g_minc2[0]);
        float cy = SUB(SUB(g_w[w * 3 + 1], g_com2[1]), g_minc2[1]);
        float cz = SUB(SUB(g_w[w * 3 + 2], g_com2[2]), g_minc2[2]);
        int ax = (int)floorf(DIV(cx, 5.0f));
        int ay = (int)floorf(DIV(cy, 5.0f));
        int az = (int)floorf(DIV(cz, 5.0f));

        int cnt = 0, base = 0;
        if (lane < 27) {
            int qx = lane % 3, qr = lane / 3;
            int qy = qr % 3, qz = qr / 3;
            int c = (ax + qx - 1) + NGRID * ((ay + qy - 1) + NGRID * (az + qz - 1));
            cnt = min(g_fill[c], CAP);
            base = c * CAP;
        }
        int incl = cnt;
#pragma unroll
        for (int o = 1; o < 32; o <<= 1) {
            int y = __shfl_up_sync(0xffffffffu, incl, o);
            if (lane >= o) incl += y;
        }
        int excl = incl - cnt;
        int T = __shfl_sync(0xffffffffu, incl, 31);
        spre[wid][lane] = excl;           // lanes >= 27 hold T (empty tail segments)
        sadj[wid][lane] = base - excl;
        __syncwarp();

        int* sjw = sj[wid];
        int cur = 0;
        for (int f0 = 0; f0 < T; f0 += 64) {
            int fA = f0 + lane;
            int fB = fA + 32;
            bool actA = (fA < T), actB = (fB < T);
            // both loads issued before either ballot (MLP = 2)
            float4 pA, pB;
            if (actA) {
                int lo = 0;
#pragma unroll
                for (int step = 16; step; step >>= 1) {
                    int nq = lo + step;
                    if (nq < 32 && spre[wid][nq] <= fA) lo = nq;
                }
                pA = g_buck[sadj[wid][lo] + fA];
            }
            if (actB) {
                int lo = 0;
#pragma unroll
                for (int step = 16; step; step >>= 1) {
                    int nq = lo + step;
                    if (nq < 32 && spre[wid][nq] <= fB) lo = nq;
                }
                pB = g_buck[sadj[wid][lo] + fB];
            }
            bool hitA = false, hitB = false;
            int jA = 0, jB = 0;
            if (actA) {
                float ddx = SUB(cx, pA.x);
                float ddy = SUB(cy, pA.y);
                float ddz = SUB(cz, pA.z);
                float r2 = ADD(ADD(MUL(ddx, ddx), MUL(ddy, ddy)), MUL(ddz, ddz));
                float dd = __fsqrt_rn(r2);
                hitA = (dd < 5.0f) && (dd > 0.001f);
                jA = __float_as_int(pA.w);
            }
            if (actB) {
                float ddx = SUB(cx, pB.x);
                float ddy = SUB(cy, pB.y);
                float ddz = SUB(cz, pB.z);
                float r2 = ADD(ADD(MUL(ddx, ddx), MUL(ddy, ddy)), MUL(ddz, ddz));
                float dd = __fsqrt_rn(r2);
                hitB = (dd < 5.0f) && (dd > 0.001f);
                jB = __float_as_int(pB.w);
            }
            unsigned balA = __ballot_sync(0xffffffffu, hitA);
            if (hitA) {
                int slot = cur + __popc(balA & ((1u << lane) - 1u));
                if (slot < MAXPA) sjw[slot] = jA;
            }
            cur += __popc(balA);
            unsigned balB = __ballot_sync(0xffffffffu, hitB);
            if (hitB) {
                int slot = cur + __popc(balB & ((1u << lane) - 1u));
                if (slot < MAXPA) sjw[slot] = jB;
            }
            cur += __popc(balB);
        }
        __syncwarp();
        int k = min(cur, MAXPA);
        // rank sort by image idx (unique) -> exact reference order
        int vals[6], rnks[6];
        int nn = 0;
        for (int i2 = lane; i2 < k; i2 += 32) {
            int v = sjw[i2];
            int r = 0;
            for (int q = 0; q < k; q++) r += (sjw[q] < v);
            vals[nn] = v;
            rnks[nn] = r;
            nn++;
        }
        __syncwarp();
        for (int q = 0; q < nn; q++) sjw[rnks[q]] = vals[q];
        __syncwarp();
        for (int r = lane; r < k; r += 32) g_slab[w * MAXPA + r] = sjw[r];
        if (lane == 0) g_cnt[w] = k;
        __syncwarp();
    }
}

// ---------------- kernel 4: redundant offset scan + ordered write + cleanup ----------------
__global__ __launch_bounds__(1024, 1)
void k_write(int N, int P, float* __restrict__ out) {
    __shared__ int soff[MAXN];
    __shared__ int stmp[32];
    int t = threadIdx.x, lane = t & 31, wid = t >> 5;

    // re-zero g_fill for next replay (previous kernels done; none here reads it)
    for (int i = blockIdx.x * 1024 + t; i < NCELL; i += gridDim.x * 1024) g_fill[i] = 0;

    // redundant block-local scan of g_cnt -> soff
    const int CH = (MAXN + 1023) / 1024;  // 4
    int lc[CH];
    int ch = (N + 1023) / 1024;
    int b0 = t * ch;
    int e0 = min(b0 + ch, N);
    int ls = 0;
    for (int i = b0; i < e0; i++) {
        int v = g_cnt[i];
        lc[i - b0] = v;
        ls += v;
    }
    int x = ls;
#pragma unroll
    for (int o = 1; o < 32; o <<= 1) {
        int y = __shfl_up_sync(0xffffffffu, x, o);
        if (lane >= o) x += y;
    }
    if (lane == 31) stmp[wid] = x;
    __syncthreads();
    if (wid == 0) {
        int s = stmp[lane];
#pragma unroll
        for (int o = 1; o < 32; o <<= 1) {
            int y = __shfl_up_sync(0xffffffffu, s, o);
            if (lane >= o) s += y;
        }
        stmp[lane] = s;
    }
    __syncthreads();
    int run = (wid ? stmp[wid - 1] : 0) + x - ls;
    for (int i = b0; i < e0; i++) {
        soff[i] = run;
        run += lc[i - b0];
    }
    __syncthreads();

    int w = blockIdx.x * 32 + wid;
    if (w >= N) return;
    int off = soff[w];
    int k = min(g_cnt[w], MAXPA);
    float fi = (float)w;
    for (int r = lane; r < k; r += 32) {
        int idx = g_slab[w * MAXPA + r];
        int s = idx / N;
        int a = idx - s * N;
        int pos = off + r;
        out[pos] = fi;
        out[P + pos] = (float)a;
        out[2 * P + 3 * pos + 0] = g_shifts2[s * 3 + 0];
        out[2 * P + 3 * pos + 1] = g_shifts2[s * 3 + 1];
        out[2 * P + 3 * pos + 2] = g_shifts2[s * 3 + 2];
    }
}

// ---------------- launch ----------------
extern "C" void kernel_launch(void* const* d_in, const int* in_sizes, int n_in,
                              void* d_out, int out_size) {
    const int* period = (const int*)d_in[0];
    const float* coords = (const float*)d_in[1];
    const float* cell = (const float*)d_in[2];
    const float* mass = (const float*)d_in[3];
    float* out = (float*)d_out;

    int N = in_sizes[1] / 3;
    int P = out_size / 5;
    int IB = (27 * N + 255) / 256;
    int WB2 = (N + 31) / 32;

    k_prep<<<1, 1024>>>(cell, period, coords, mass, N);
    k_image<<<IB, 256>>>(N);
    k_search<<<SGRID, 256>>>(N);
    k_write<<<WB2, 1024>>>(N, P, out);
}

// round 12
// speedup vs baseline: 1.2732x; 1.2732x over previous
#include <cuda_runtime.h>
#include <math.h>

#define MAXN 4096
#define MAXS 27
#define NGRID 10
#define NCELL (NGRID * NGRID * NGRID)
#define MAXPA 192
#define CAP 64
#define CAPL 128   // per-half-list capacity in k_search

__device__ float  g_w[MAXN * 3];
__device__ float  g_shifts2[MAXS * 3];
__device__ int    g_S;
__device__ float  g_com2[3], g_minc2[3], g_maxc2[3];
__device__ int    g_fill[NCELL];          // zero at load; re-zeroed by k_write every run
__device__ float4 g_buck[NCELL * CAP];    // 1 MB fixed-capacity buckets
__device__ int    g_slab[MAXN * MAXPA];
__device__ int    g_cnt[MAXN];

#define MUL(a, b) __fmul_rn((a), (b))
#define ADD(a, b) __fadd_rn((a), (b))
#define SUB(a, b) __fsub_rn((a), (b))
#define DIV(a, b) __fdiv_rn((a), (b))

__device__ __forceinline__ unsigned fkey(float f) {
    unsigned u = __float_as_uint(f);
    return (u & 0x80000000u) ? ~u : (u | 0x80000000u);
}
__device__ __forceinline__ float fdec(unsigned k) {
    unsigned u = (k & 0x80000000u) ? (k & 0x7fffffffu) : ~k;
    return __uint_as_float(u);
}

// ---------------- kernel 1: setup (redundant per block) + partitioned wrap ----------------
__global__ void k_wrap(const float* __restrict__ cell, const int* __restrict__ period,
                       const float* __restrict__ coords, int N) {
    __shared__ float sinv[9], sfrac0[3];
    int t = threadIdx.x, b = blockIdx.x;
    if (t == 0) {
        float m00 = cell[0], m01 = cell[1], m02 = cell[2];
        float m10 = cell[3], m11 = cell[4], m12 = cell[5];
        float m20 = cell[6], m21 = cell[7], m22 = cell[8];
        float c00 = SUB(MUL(m11, m22), MUL(m12, m21));
        float c10 = SUB(MUL(m12, m20), MUL(m10, m22));
        float c20 = SUB(MUL(m10, m21), MUL(m11, m20));
        float det = ADD(ADD(MUL(m00, c00), MUL(m01, c10)), MUL(m02, c20));
        sinv[0] = DIV(c00, det);
        sinv[1] = DIV(SUB(MUL(m02, m21), MUL(m01, m22)), det);
        sinv[2] = DIV(SUB(MUL(m01, m12), MUL(m02, m11)), det);
        sinv[3] = DIV(c10, det);
        sinv[4] = DIV(SUB(MUL(m00, m22), MUL(m02, m20)), det);
        sinv[5] = DIV(SUB(MUL(m02, m10), MUL(m00, m12)), det);
        sinv[6] = DIV(c20, det);
        sinv[7] = DIV(SUB(MUL(m01, m20), MUL(m00, m21)), det);
        sinv[8] = DIV(SUB(MUL(m00, m11), MUL(m01, m10)), det);
        float x0 = coords[0], y0 = coords[1], z0 = coords[2];
        for (int d = 0; d < 3; d++)
            sfrac0[d] = ADD(ADD(MUL(x0, sinv[0 + d]), MUL(y0, sinv[3 + d])), MUL(z0, sinv[6 + d]));
        if (b == 0) {
            int nrep[3];
            for (int i = 0; i < 3; i++) {
                float r = DIV(5.0f, fabsf(cell[0 + i]));
                float r1 = DIV(5.0f, fabsf(cell[3 + i]));
                float r2 = DIV(5.0f, fabsf(cell[6 + i]));
                if (r1 < r) r = r1;
                if (r2 < r) r = r2;
                nrep[i] = (int)ceilf(r) * period[i];
            }
            int idx = 0;
            for (int a = -nrep[0]; a <= nrep[0]; a++)
                for (int bb = -nrep[1]; bb <= nrep[1]; bb++)
                    for (int c = -nrep[2]; c <= nrep[2]; c++) {
                        if (idx < MAXS) {
                            float fa = (float)a, fb = (float)bb, fc = (float)c;
                            for (int d = 0; d < 3; d++)
                                g_shifts2[idx * 3 + d] =
                                    ADD(ADD(MUL(fa, cell[0 + d]), MUL(fb, cell[3 + d])), MUL(fc, cell[6 + d]));
                        }
                        idx++;
                    }
            g_S = (idx > MAXS) ? MAXS : idx;
        }
    }
    __syncthreads();
    int i = b * 256 + t;
    if (i < N) {
        float x = coords[i * 3 + 0], y = coords[i * 3 + 1], z = coords[i * 3 + 2];
        float f[3];
        for (int d = 0; d < 3; d++)
            f[d] = ADD(ADD(MUL(x, sinv[0 + d]), MUL(y, sinv[3 + d])), MUL(z, sinv[6 + d]));
        for (int d = 0; d < 3; d++)
            f[d] = SUB(f[d], rintf(SUB(f[d], sfrac0[d])));
        g_w[i * 3 + 0] = ADD(ADD(MUL(f[0], cell[0]), MUL(f[1], cell[3])), MUL(f[2], cell[6]));
        g_w[i * 3 + 1] = ADD(ADD(MUL(f[0], cell[1]), MUL(f[1], cell[4])), MUL(f[2], cell[7]));
        g_w[i * 3 + 2] = ADD(ADD(MUL(f[0], cell[2]), MUL(f[1], cell[5])), MUL(f[2], cell[8]));
    }
}

// ---------------- kernel 2: COM + min/max (single block, bit-identical order) ----------------
__global__ __launch_bounds__(1024, 1)
void k_reduce(const float* __restrict__ mass, int N) {
    __shared__ double sd[4096];
    __shared__ unsigned skey6[32][6];
    __shared__ float scom[3];
    int t = threadIdx.x, lane = t & 31, wid = t >> 5;

    double s0 = 0.0, s1 = 0.0, s2 = 0.0, s3 = 0.0;
    for (int i = t; i < N; i += 1024) {
        double m = (double)mass[i];
        s0 += m * (double)g_w[i * 3 + 0];
        s1 += m * (double)g_w[i * 3 + 1];
        s2 += m * (double)g_w[i * 3 + 2];
        s3 += m;
    }
    sd[t] = s0; sd[1024 + t] = s1; sd[2048 + t] = s2; sd[3072 + t] = s3;
    __syncthreads();
#pragma unroll
    for (int off = 512; off >= 32; off >>= 1) {
        if (t < off) {
            sd[t] += sd[t + off];
            sd[1024 + t] += sd[1024 + t + off];
            sd[2048 + t] += sd[2048 + t + off];
            sd[3072 + t] += sd[3072 + t + off];
        }
        __syncthreads();
    }
    if (wid == 0) {
        double x0 = sd[lane], x1 = sd[1024 + lane], x2 = sd[2048 + lane], x3 = sd[3072 + lane];
#pragma unroll
        for (int off = 16; off >= 1; off >>= 1) {
            x0 += __shfl_down_sync(0xffffffffu, x0, off);
            x1 += __shfl_down_sync(0xffffffffu, x1, off);
            x2 += __shfl_down_sync(0xffffffffu, x2, off);
            x3 += __shfl_down_sync(0xffffffffu, x3, off);
        }
        if (lane == 0) {
            float sm = (float)x3;
            scom[0] = DIV((float)x0, sm);
            scom[1] = DIV((float)x1, sm);
            scom[2] = DIV((float)x2, sm);
            g_com2[0] = scom[0]; g_com2[1] = scom[1]; g_com2[2] = scom[2];
        }
    }
    __syncthreads();

    unsigned kmn[3] = {~0u, ~0u, ~0u}, kmx[3] = {0u, 0u, 0u};
    for (int i = t; i < N; i += 1024) {
        unsigned k0 = fkey(SUB(g_w[i * 3 + 0], scom[0]));
        unsigned k1 = fkey(SUB(g_w[i * 3 + 1], scom[1]));
        unsigned k2 = fkey(SUB(g_w[i * 3 + 2], scom[2]));
        kmn[0] = min(kmn[0], k0); kmx[0] = max(kmx[0], k0);
        kmn[1] = min(kmn[1], k1); kmx[1] = max(kmx[1], k1);
        kmn[2] = min(kmn[2], k2); kmx[2] = max(kmx[2], k2);
    }
#pragma unroll
    for (int o = 16; o; o >>= 1) {
#pragma unroll
        for (int d = 0; d < 3; d++) {
            kmn[d] = min(kmn[d], __shfl_xor_sync(0xffffffffu, kmn[d], o));
            kmx[d] = max(kmx[d], __shfl_xor_sync(0xffffffffu, kmx[d], o));
        }
    }
    if (lane == 0) {
#pragma unroll
        for (int d = 0; d < 3; d++) {
            skey6[wid][d] = kmn[d];
            skey6[wid][3 + d] = kmx[d];
        }
    }
    __syncthreads();
    if (wid == 0) {
        unsigned vn0 = skey6[lane][0], vn1 = skey6[lane][1], vn2 = skey6[lane][2];
        unsigned vx0 = skey6[lane][3], vx1 = skey6[lane][4], vx2 = skey6[lane][5];
#pragma unroll
        for (int o = 16; o; o >>= 1) {
            vn0 = min(vn0, __shfl_xor_sync(0xffffffffu, vn0, o));
            vn1 = min(vn1, __shfl_xor_sync(0xffffffffu, vn1, o));
            vn2 = min(vn2, __shfl_xor_sync(0xffffffffu, vn2, o));
            vx0 = max(vx0, __shfl_xor_sync(0xffffffffu, vx0, o));
            vx1 = max(vx1, __shfl_xor_sync(0xffffffffu, vx1, o));
            vx2 = max(vx2, __shfl_xor_sync(0xffffffffu, vx2, o));
        }
        if (lane == 0) {
            float mn0 = SUB(SUB(fdec(vn0), 5.0f), 1e-6f);
            float mn1 = SUB(SUB(fdec(vn1), 5.0f), 1e-6f);
            float mn2 = SUB(SUB(fdec(vn2), 5.0f), 1e-6f);
            g_minc2[0] = mn0; g_minc2[1] = mn1; g_minc2[2] = mn2;
            g_maxc2[0] = ADD(SUB(fdec(vx0), mn0), 5.0f);
            g_maxc2[1] = ADD(SUB(fdec(vx1), mn1), 5.0f);
            g_maxc2[2] = ADD(SUB(fdec(vx2), mn2), 5.0f);
        }
    }
}

// ---------------- kernel 3: images -> fixed-capacity buckets (one thread per image) --------
__global__ void k_image(int N) {
    int gt = blockIdx.x * 256 + threadIdx.x;
    int NS = g_S * N;
    if (gt >= NS) return;
    int s = gt / N;
    int a = gt - s * N;
    float c2x = SUB(SUB(g_w[a * 3 + 0], g_com2[0]), g_minc2[0]);
    float c2y = SUB(SUB(g_w[a * 3 + 1], g_com2[1]), g_minc2[1]);
    float c2z = SUB(SUB(g_w[a * 3 + 2], g_com2[2]), g_minc2[2]);
    float v0 = ADD(c2x, g_shifts2[s * 3 + 0]);
    float v1 = ADD(c2y, g_shifts2[s * 3 + 1]);
    float v2 = ADD(c2z, g_shifts2[s * 3 + 2]);
    if ((v0 > 0.f) && (v0 < g_maxc2[0]) && (v1 > 0.f) && (v1 < g_maxc2[1]) &&
        (v2 > 0.f) && (v2 < g_maxc2[2])) {
        int cx = min(max((int)floorf(DIV(v0, 5.0f)), 0), NGRID - 1);
        int cy = min(max((int)floorf(DIV(v1, 5.0f)), 0), NGRID - 1);
        int cz = min(max((int)floorf(DIV(v2, 5.0f)), 0), NGRID - 1);
        int c = cx + NGRID * (cy + NGRID * cz);
        int pos = atomicAdd(&g_fill[c], 1);
        if (pos < CAP)
            g_buck[c * CAP + pos] = make_float4(v0, v1, v2, __int_as_float(gt));
    }
}

// ---------------- kernel 4: search, TWO warps per atom (parity-split chunks) ----------------
__global__ __launch_bounds__(256, 1)
void k_search(int N) {
    __shared__ int sj2[4][2][CAPL];
    __shared__ int scnt2[4][2];
    __shared__ int spre[4][32];
    __shared__ int sadj[4][32];
    int t = threadIdx.x, lane = t & 31, wid = t >> 5;
    int pr = wid >> 1, p = wid & 1;          // pair id (atom slot), parity
    int w = blockIdx.x * 4 + pr;
    bool active = (w < N);

    float cx = 0.f, cy = 0.f, cz = 0.f;
    int T = 0;
    if (active) {
        cx = SUB(SUB(g_w[w * 3 + 0], g_com2[0]), g_minc2[0]);
        cy = SUB(SUB(g_w[w * 3 + 1], g_com2[1]), g_minc2[1]);
        cz = SUB(SUB(g_w[w * 3 + 2], g_com2[2]), g_minc2[2]);
        int ax = (int)floorf(DIV(cx, 5.0f));
        int ay = (int)floorf(DIV(cy, 5.0f));
        int az = (int)floorf(DIV(cz, 5.0f));

        int cnt = 0, base = 0;
        if (lane < 27) {
            int qx = lane % 3, qr = lane / 3;
            int qy = qr % 3, qz = qr / 3;
            int c = (ax + qx - 1) + NGRID * ((ay + qy - 1) + NGRID * (az + qz - 1));
            cnt = min(g_fill[c], CAP);
            base = c * CAP;
        }
        int incl = cnt;
#pragma unroll
        for (int o = 1; o < 32; o <<= 1) {
            int y = __shfl_up_sync(0xffffffffu, incl, o);
            if (lane >= o) incl += y;
        }
        int excl = incl - cnt;
        T = __shfl_sync(0xffffffffu, incl, 31);
        if (p == 0) {
            spre[pr][lane] = excl;        // lanes >= 27 hold T (empty tail segments)
            sadj[pr][lane] = base - excl;
        }
    }
    __syncthreads();

    int cur = 0;
    if (active) {
        int* sjw = sj2[pr][p];
        for (int f0 = p * 32; f0 < T; f0 += 64) {   // parity warps take alternating chunks
            int f = f0 + lane;
            bool hit = false;
            int jidx = 0;
            if (f < T) {
                int lo = 0;
#pragma unroll
                for (int step = 16; step; step >>= 1) {
                    int nq = lo + step;
                    if (nq < 32 && spre[pr][nq] <= f) lo = nq;
                }
                float4 pq = g_buck[sadj[pr][lo] + f];
                float ddx = SUB(cx, pq.x);
                float ddy = SUB(cy, pq.y);
                float ddz = SUB(cz, pq.z);
                float r2 = ADD(ADD(MUL(ddx, ddx), MUL(ddy, ddy)), MUL(ddz, ddz));
                float dd = __fsqrt_rn(r2);
                hit = (dd < 5.0f) && (dd > 0.001f);
                jidx = __float_as_int(pq.w);
            }
            unsigned bal = __ballot_sync(0xffffffffu, hit);
            if (hit) {
                int slot = cur + __popc(bal & ((1u << lane) - 1u));
                if (slot < CAPL) sjw[slot] = jidx;
            }
            cur += __popc(bal);
        }
        if (lane == 0) scnt2[pr][p] = min(cur, CAPL);
    }
    __syncthreads();

    if (active) {
        // merged rank-sort: image indices unique, lists disjoint -> ranks unique,
        // ascending idx == exact reference order
        int k0 = scnt2[pr][0], k1 = scnt2[pr][1];
        int k = k0 + k1;
        const int* l0 = sj2[pr][0];
        const int* l1 = sj2[pr][1];
        for (int idx = p * 32 + lane; idx < k; idx += 64) {
            int v = (idx < k0) ? l0[idx] : l1[idx - k0];
            int r = 0;
            for (int q = 0; q < k0; q++) r += (l0[q] < v);
            for (int q = 0; q < k1; q++) r += (l1[q] < v);
            if (r < MAXPA) g_slab[w * MAXPA + r] = v;
        }
        if (p == 0 && lane == 0) g_cnt[w] = min(k, MAXPA);
    }
}

// ---------------- kernel 5: redundant offset scan + ordered write + cleanup ----------------
__global__ void k_write(int N, int P, float* __restrict__ out) {
    __shared__ int soff[MAXN];
    __shared__ int stmp[8];
    int t = threadIdx.x, lane = t & 31, wid = t >> 5;

    // re-zero g_fill for next run (previous kernels done; none here reads it)
    for (int i = blockIdx.x * 256 + t; i < NCELL; i += gridDim.x * 256) g_fill[i] = 0;

    // redundant block-local scan of g_cnt -> soff
    const int E = (MAXN + 255) / 256;  // 16
    int lc[E];
    int b0 = t * ((N + 255) / 256);
    int e0 = min(b0 + (N + 255) / 256, N);
    int ls = 0;
    for (int i = b0; i < e0; i++) {
        int v = g_cnt[i];
        lc[i - b0] = v;
        ls += v;
    }
    int x = ls;
#pragma unroll
    for (int o = 1; o < 32; o <<= 1) {
        int y = __shfl_up_sync(0xffffffffu, x, o);
        if (lane >= o) x += y;
    }
    if (lane == 31) stmp[wid] = x;
    __syncthreads();
    if (wid == 0 && lane < 8) {
        int s = stmp[lane];
#pragma unroll
        for (int o = 1; o < 8; o <<= 1) {
            int y = __shfl_up_sync(0xffu, s, o);
            if (lane >= o) s += y;
        }
        stmp[lane] = s;
    }
    __syncthreads();
    int run = (wid ? stmp[wid - 1] : 0) + x - ls;
    for (int i = b0; i < e0; i++) {
        soff[i] = run;
        run += lc[i - b0];
    }
    __syncthreads();

    int w = blockIdx.x * 8 + wid;
    if (w >= N) return;
    int off = soff[w];
    int k = min(g_cnt[w], MAXPA);
    float fi = (float)w;
    for (int r = lane; r < k; r += 32) {
        int idx = g_slab[w * MAXPA + r];
        int s = idx / N;
        int a = idx - s * N;
        int pos = off + r;
        out[pos] = fi;
        out[P + pos] = (float)a;
        out[2 * P + 3 * pos + 0] = g_shifts2[s * 3 + 0];
        out[2 * P + 3 * pos + 1] = g_shifts2[s * 3 + 1];
        out[2 * P + 3 * pos + 2] = g_shifts2[s * 3 + 2];
    }
}

// ---------------- launch ----------------
extern "C" void kernel_launch(void* const* d_in, const int* in_sizes, int n_in,
                              void* d_out, int out_size) {
    const int* period = (const int*)d_in[0];
    const float* coords = (const float*)d_in[1];
    const float* cell = (const float*)d_in[2];
    const float* mass = (const float*)d_in[3];
    float* out = (float*)d_out;

    int N = in_sizes[1] / 3;
    int P = out_size / 5;
    int WB = (N + 255) / 256;
    int IB = (27 * N + 255) / 256;
    int SB4 = (N + 3) / 4;   // 2 warps per atom, 4 atoms per 256-thread block
    int SB = (N + 7) / 8;

    k_wrap<<<WB, 256>>>(cell, period, coords, N);
    k_reduce<<<1, 1024>>>(mass, N);
    k_image<<<IB, 256>>>(N);
    k_search<<<SB4, 256>>>(N);
    k_write<<<SB, 256>>>(N, P, out);
}